// round 12
// baseline (speedup 1.0000x reference)
#include <cuda_runtime.h>
#include <cuda_bf16.h>
#include <math.h>

#define KT  23
#define TSTART 21
#define TSTOP  22
#define NEGV (-10000.0f)
#define TN  8192
#define EE  50
#define HHD 128
#define GG  512   // 4*HHD

// ---------------- device scratch (static, no allocations) ----------------
__device__ float d_pre[2u * TN * GG];          // 32 MB  pre-gates per dir/time
__device__ float d_houtg[2u * TN * HHD];       // 8 MB   hidden states per dir/time
__device__ float d_feats[TN * KT];             // 753 KB
__device__ float d_fvrow[TN * 32];             // 1 MB   viterbi fv rows (padded to 32)
__device__ unsigned char d_bp[TN * KT];        // 184 KB backpointers
__device__ float d_score_g;
__device__ int   d_last_tag;
__device__ int   d_tags_g[TN];

// ---------------- helpers ----------------
__device__ __forceinline__ void fma2(unsigned long long& d,
                                     unsigned long long a,
                                     unsigned long long b) {
    asm("fma.rn.f32x2 %0, %1, %2, %0;" : "+l"(d) : "l"(a), "l"(b));
}
__device__ __forceinline__ float ull_lo(unsigned long long v) {
    return __uint_as_float((unsigned)(v & 0xffffffffull));
}
__device__ __forceinline__ float ull_hi(unsigned long long v) {
    return __uint_as_float((unsigned)(v >> 32));
}
__device__ __forceinline__ float ex2f(float x) {
    float r; asm("ex2.approx.ftz.f32 %0, %1;" : "=f"(r) : "f"(x)); return r;
}
__device__ __forceinline__ float rcpf(float x) {
    float r; asm("rcp.approx.ftz.f32 %0, %1;" : "=f"(r) : "f"(x)); return r;
}
__device__ __forceinline__ unsigned smem_u32(const void* p) {
    unsigned a;
    asm("{ .reg .u64 t; cvta.to.shared.u64 t, %1; cvt.u32.u64 %0, t; }"
        : "=r"(a) : "l"(p));
    return a;
}
__device__ __forceinline__ unsigned mapa_u32(unsigned local_addr, unsigned peer_rank) {
    unsigned r;
    asm("mapa.shared::cluster.u32 %0, %1, %2;" : "=r"(r) : "r"(local_addr), "r"(peer_rank));
    return r;
}
// predicated triple store: local smem, peer DSMEM, global — only when sub==0
__device__ __forceinline__ void stores_pred(int sub, unsigned a_loc, unsigned a_rem,
                                            float* gptr, float hn) {
    asm volatile(
        "{\n\t.reg .pred p;\n\t"
        "setp.eq.s32 p, %0, 0;\n\t"
        "@p st.shared.f32 [%1], %4;\n\t"
        "@p st.shared::cluster.f32 [%2], %4;\n\t"
        "@p st.global.f32 [%3], %4;\n\t}"
        :: "r"(sub), "r"(a_loc), "r"(a_rem), "l"(gptr), "f"(hn) : "memory");
}
// predicated release-arrive on (already mapa'd) peer mbar — only lane 0
__device__ __forceinline__ void arrive_pred(int lane, unsigned ra_mbar) {
    asm volatile(
        "{\n\t.reg .pred p;\n\t"
        "setp.eq.s32 p, %0, 0;\n\t"
        "@p mbarrier.arrive.release.cluster.shared::cluster.b64 _, [%1];\n\t}"
        :: "r"(lane), "r"(ra_mbar) : "memory");
}
__device__ __forceinline__ void mbar_wait_parity_cluster(unsigned mbar, unsigned parity) {
    asm volatile(
        "{\n\t.reg .pred P;\n\t"
        "W_%=:\n\t"
        "mbarrier.try_wait.parity.acquire.cluster.shared::cta.b64 P, [%0], %1, 0x989680;\n\t"
        "@P bra.uni D_%=;\n\t"
        "bra.uni W_%=;\n\t"
        "D_%=:\n\t}"
        :: "r"(mbar), "r"(parity) : "memory");
}

// ---------------- kernel 1: embedding + input-gate precompute ----------------
__global__ void pre_kernel(const int* __restrict__ sentence,
                           const float* __restrict__ embed,
                           const float* __restrict__ Wih_f,
                           const float* __restrict__ bih_f,
                           const float* __restrict__ bhh_f,
                           const float* __restrict__ Wih_b,
                           const float* __restrict__ bih_b,
                           const float* __restrict__ bhh_b) {
    const int TT = 64;
    __shared__ float sx[TT * EE];
    int t0 = blockIdx.x * TT;
    int tid = threadIdx.x;   // 512
    for (int idx = tid; idx < TT * EE; idx += 512) {
        int tl = idx / EE, e = idx - tl * EE;
        sx[idx] = embed[(size_t)sentence[t0 + tl] * EE + e];
    }
    __syncthreads();
    int r = tid;
    for (int d = 0; d < 2; d++) {
        const float* Wih = d ? Wih_b : Wih_f;
        const float* bi  = d ? bih_b : bih_f;
        const float* bh  = d ? bhh_b : bhh_f;
        float w[EE];
#pragma unroll
        for (int e = 0; e < EE; e++) w[e] = Wih[r * EE + e];
        float bs = bi[r] + bh[r];
        for (int tl = 0; tl < TT; tl++) {
            float acc = bs;
#pragma unroll
            for (int e = 0; e < EE; e++) acc += w[e] * sx[tl * EE + e];
            d_pre[((size_t)d * TN + (t0 + tl)) * GG + r] = acc;
        }
    }
}

// ---------------- dummy (positions ncu capture window on lstm) -------------
__global__ void dummy_kernel() {}

// ---------------- kernel 2: sequential LSTM (branch-minimal loop) ----------
// 2 CTAs per direction (cluster 2). CTA q owns hidden dims [64q,64q+64).
// 256 threads = 8 warps: w=tid>>5, l=lane, quad=l>>2, sub=l&3 (gate i,f,g,o).
// dim = 64q + w*8 + quad; row R = sub*128 + dim; 128 weight cols in regs.
// Per step: phase A local-half FMA, uncond mbar wait (parity=s&1, pre-loop
// arrival covers s=0), phase C remote-half FMA, per-lane activation,
// quad-gather shfl, REDUNDANT cell math in all 4 sub-lanes (no divergence),
// predicated scalar stores, __syncwarp + per-warp predicated release-arrive,
// then __syncthreads (off the inter-CTA path, overlaps DSMEM flight).
#define FMA_HALF(H0, W0) do {                                              \
    _Pragma("unroll")                                                      \
    for (int k2 = 0; k2 < 8; k2++) {                                       \
        ulonglong2 hva = h2[(H0) + 2 * k2];                                \
        ulonglong2 hvb = h2[(H0) + 2 * k2 + 1];                            \
        fma2(aA, wr[(W0) + 4 * k2 + 0], hva.x);                            \
        fma2(aB, wr[(W0) + 4 * k2 + 1], hva.y);                            \
        fma2(aA, wr[(W0) + 4 * k2 + 2], hvb.x);                            \
        fma2(aB, wr[(W0) + 4 * k2 + 3], hvb.y);                            \
    }                                                                      \
} while (0)

__global__ void __cluster_dims__(2, 1, 1) __launch_bounds__(256, 1)
lstm_kernel(const float* __restrict__ Whh_f,
            const float* __restrict__ Whh_b,
            const float* __restrict__ h0,
            const float* __restrict__ c0) {
    __shared__ float s_h[2][HHD];
    __shared__ __align__(8) unsigned long long s_mbar;

    const int dir = blockIdx.x >> 1;
    unsigned q;
    asm("mov.u32 %0, %%cluster_ctarank;" : "=r"(q));
    const unsigned peer = q ^ 1u;

    const int tid  = threadIdx.x;
    const int w    = tid >> 5;
    const int l    = tid & 31;
    const int quad = l >> 2;
    const int sub  = l & 3;
    const int dimg = (int)(64u * q) + w * 8 + quad;   // global hidden dim
    const int R    = sub * HHD + dimg;                // gate row

    const float* Whh = dir ? Whh_b : Whh_f;

    unsigned long long wr[64];
    const unsigned long long* wrow = (const unsigned long long*)(Whh + (size_t)R * HHD);
#pragma unroll
    for (int k = 0; k < 64; k++) wr[k] = wrow[k];

    if (tid < HHD) s_h[0][tid] = h0[dir * HHD + tid];
    float c = c0[dir * HHD + dimg];                   // carried redundantly in all 4 sub-lanes

    unsigned mbar_addr = smem_u32(&s_mbar);
    if (tid == 0) {
        asm volatile("mbarrier.init.shared.b64 [%0], 8;" :: "r"(mbar_addr) : "memory");
    }
    __syncthreads();
    asm volatile("barrier.cluster.arrive.aligned;" ::: "memory");
    asm volatile("barrier.cluster.wait.aligned;" ::: "memory");

    // hoisted peer addresses (mapa is pure address math)
    unsigned ra_mbar = mapa_u32(mbar_addr, peer);
    unsigned a_loc0 = smem_u32(&s_h[0][dimg]);
    unsigned a_loc1 = smem_u32(&s_h[1][dimg]);
    unsigned a_rem0 = mapa_u32(a_loc0, peer);
    unsigned a_rem1 = mapa_u32(a_loc1, peer);

    // pre-loop arrival: completes phase 0 so the in-loop wait is unconditional
    arrive_pred(l, ra_mbar);

    const float* preR = d_pre + (size_t)dir * TN * GG + R;
    const int dt = dir ? -1 : 1;
    const int t0i = dir ? (TN - 1) : 0;
    float* gp = d_houtg + (size_t)dir * TN * HHD + (size_t)t0i * HHD + dimg;
    const ptrdiff_t gstep = (ptrdiff_t)dt * HHD;

    const float LOG2E   = 1.4426950408889634f;
    const float sc_mine = (sub == 2) ? 2.0f * LOG2E : -LOG2E;   // tanh(g) vs sigmoid

    // depth-2 pre[] prefetch pipeline
    float pv0 = __ldg(preR + (size_t)t0i * GG);
    float pv1 = __ldg(preR + (size_t)(t0i + dt) * GG);

    for (int s = 0; s < TN; s++) {
        const int cur = s & 1;
        float pv = pv0;
        pv0 = pv1;
        int t2 = dir ? (TN - 3 - s) : (s + 2);
        t2 = min(max(t2, 0), TN - 1);                       // clamp, branch-free
        pv1 = __ldg(preR + (size_t)t2 * GG);

        const ulonglong2* h2 = (const ulonglong2*)s_h[cur];
        unsigned long long aA = 0ull, aB = 0ull;

        // phase A: local half (written locally last step, covered by bar)
        if (q == 0) { FMA_HALF(0, 0); } else { FMA_HALF(16, 32); }

        // phase B: wait for peer half (phase s; phase 0 pre-arrived)
        mbar_wait_parity_cluster(mbar_addr, (unsigned)(s & 1));

        // phase C: remote half
        if (q == 0) { FMA_HALF(16, 32); } else { FMA_HALF(0, 0); }

        float partial = (ull_lo(aA) + ull_hi(aA)) + (ull_lo(aB) + ull_hi(aB)) + pv;

        // per-lane unified nonlinearity: sigma = 1/(1+e^{-x}); tanh = 1-2/(1+e^{2x})
        float e = ex2f(sc_mine * partial);
        float dnm = rcpf(1.0f + e);
        float a = (sub == 2) ? fmaf(-2.0f, dnm, 1.0f) : dnm;

        // broadcast the quad's 4 activations to all 4 lanes
        int base = l & ~3;
        float ai = __shfl_sync(0xffffffffu, a, base);
        float af = __shfl_sync(0xffffffffu, a, base + 1);
        float ag = __shfl_sync(0xffffffffu, a, base + 2);
        float ao = __shfl_sync(0xffffffffu, a, base + 3);

        // redundant cell update in all 4 sub-lanes (identical values, no branch)
        c = fmaf(af, c, ai * ag);
        float e2 = ex2f(2.0f * LOG2E * c);
        float tc = fmaf(-2.0f, rcpf(1.0f + e2), 1.0f);
        float hn = ao * tc;

        // predicated stores from sub==0 lanes: local buf, peer buf, global
        unsigned la = cur ? a_loc0 : a_loc1;                // write buffer (s+1)&1
        unsigned ra = cur ? a_rem0 : a_rem1;
        stores_pred(sub, la, ra, gp, hn);
        gp += gstep;

        __syncwarp();                                       // order quad stores before arrive
        arrive_pred(l, ra_mbar);                            // per-warp release to peer
        __syncthreads();                                    // local buffer coherence only
    }
    asm volatile("barrier.cluster.arrive.aligned;" ::: "memory");
    asm volatile("barrier.cluster.wait.aligned;" ::: "memory");
}

// ---------------- kernel 3: output projection ----------------
__global__ void feats_kernel(const float* __restrict__ W_out,
                             const float* __restrict__ b_out) {
    int t = blockIdx.x;
    int tid = threadIdx.x;   // 256
    __shared__ float s_hc[256];
    s_hc[tid] = (tid < HHD) ? d_houtg[(size_t)t * HHD + tid]
                            : d_houtg[(size_t)TN * HHD + (size_t)t * HHD + (tid - HHD)];
    __syncthreads();
    int w = tid >> 5, l = tid & 31;
    for (int k = w; k < KT; k += 8) {
        float acc = 0.0f;
#pragma unroll
        for (int jj = l; jj < 256; jj += 32) acc += W_out[k * 256 + jj] * s_hc[jj];
#pragma unroll
        for (int off = 16; off; off >>= 1) acc += __shfl_down_sync(0xffffffffu, acc, off);
        if (l == 0) d_feats[t * KT + k] = acc + b_out[k];
    }
}

// ---------------- kernel 4a: Viterbi forward (values only) ----------------
__global__ void viterbi_fwd_kernel(const float* __restrict__ transitions) {
    int lane = threadIdx.x;
    bool act = lane < KT;
    float tr[KT];
#pragma unroll
    for (int p = 0; p < KT; p++) {
        float v = NEGV;
        if (act) {
            v = transitions[lane * KT + p];
            if (lane == TSTART) v = NEGV;
            if (p == TSTOP)     v = NEGV;
        }
        tr[p] = v;
    }
    float trS = act ? ((lane == TSTOP) ? NEGV : transitions[TSTOP * KT + lane]) : NEGV;
    float fv = (lane == TSTART) ? 0.0f : NEGV;

    float f0 = act ? d_feats[0 * KT + lane] : 0.0f;
    float f1 = act ? d_feats[1 * KT + lane] : 0.0f;
    float f2 = act ? d_feats[2 * KT + lane] : 0.0f;

    for (int t = 0; t < TN; t++) {
        float fn = 0.0f;
        if (act && t + 3 < TN) fn = d_feats[(t + 3) * KT + lane];

        d_fvrow[t * 32 + lane] = fv;   // fv BEFORE step t (for bp recompute)

        float cc[24];
#pragma unroll
        for (int p = 0; p < KT; p++) cc[p] = __shfl_sync(0xffffffffu, fv, p) + tr[p];
        cc[23] = -3.0e38f;

        float a[12];
#pragma unroll
        for (int p = 0; p < 12; p++) a[p] = fmaxf(cc[2 * p], cc[2 * p + 1]);
        float b[6];
#pragma unroll
        for (int p = 0; p < 6; p++) b[p] = fmaxf(a[2 * p], a[2 * p + 1]);
        float c3[3];
#pragma unroll
        for (int p = 0; p < 3; p++) c3[p] = fmaxf(b[2 * p], b[2 * p + 1]);
        float best = fmaxf(fmaxf(c3[0], c3[1]), c3[2]);

        fv = best + f0;
        f0 = f1; f1 = f2; f2 = fn;
    }

    float term = act ? (fv + trS) : NEGV;
    int idx = lane;
#pragma unroll
    for (int off = 16; off; off >>= 1) {
        float ov = __shfl_down_sync(0xffffffffu, term, off);
        int   oi = __shfl_down_sync(0xffffffffu, idx,  off);
        if (ov > term || (ov == term && oi < idx)) { term = ov; idx = oi; }
    }
    __syncwarp();
    if (lane == 0) { d_score_g = term; d_last_tag = idx; }
}

// ---------------- kernel 4b: backpointer recompute (parallel over t) -------
__global__ void viterbi_bp_kernel(const float* __restrict__ transitions) {
    int wrp = threadIdx.x >> 5, lane = threadIdx.x & 31;
    int t = blockIdx.x * 8 + wrp;
    if (t >= TN) return;
    int k = lane;
    bool act = k < KT;

    float tr[KT];   // tr[p] = trans[k][p] constrained
#pragma unroll
    for (int p = 0; p < KT; p++) {
        float v = NEGV;
        if (act) {
            v = __ldg(&transitions[k * KT + p]);
            if (k == TSTART) v = NEGV;
            if (p == TSTOP)  v = NEGV;
        }
        tr[p] = v;
    }
    float fvv = d_fvrow[t * 32 + lane];

    float best = __shfl_sync(0xffffffffu, fvv, 0) + tr[0];
    int bp = 0;
#pragma unroll
    for (int p = 1; p < KT; p++) {
        float v = __shfl_sync(0xffffffffu, fvv, p) + tr[p];
        if (v > best) { best = v; bp = p; }   // first-argmax semantics
    }
    if (act) d_bp[t * KT + k] = (unsigned char)bp;
}

// ---------------- kernel 4c: backtrace over smem-staged bp table -----------
__global__ void viterbi_bt_kernel() {
    extern __shared__ unsigned char sbp[];   // TN * KT bytes
    int tid = threadIdx.x;
    const uint4* src = (const uint4*)d_bp;
    uint4* dst = (uint4*)sbp;
    for (int i = tid; i < (TN * KT) / 16; i += blockDim.x) dst[i] = src[i];
    __syncthreads();
    if (tid == 0) {
        int tag = d_last_tag;
        d_tags_g[TN - 1] = tag;
        for (int t = TN - 1; t > 0; t--) {
            tag = sbp[t * KT + tag];
            d_tags_g[t - 1] = tag;
        }
    }
}

// ---------------- kernel 5: write output ----------------
__global__ void epilogue_kernel(float* __restrict__ out, int n) {
    int i = blockIdx.x * blockDim.x + threadIdx.x;
    if (i >= n) return;
    float v;
    if (n == TN) {
        v = (float)d_tags_g[i];
    } else if (n == 1) {
        v = d_score_g;
    } else {
        v = (i == 0) ? d_score_g
                     : ((i - 1 < TN) ? (float)d_tags_g[i - 1] : 0.0f);
    }
    out[i] = v;
}

// ---------------- launch ----------------
extern "C" void kernel_launch(void* const* d_in, const int* in_sizes, int n_in,
                              void* d_out, int out_size) {
    const int*   sentence = (const int*)  d_in[0];
    const float* embed    = (const float*)d_in[1];
    const float* Wih_f    = (const float*)d_in[2];
    const float* Whh_f    = (const float*)d_in[3];
    const float* bih_f    = (const float*)d_in[4];
    const float* bhh_f    = (const float*)d_in[5];
    const float* Wih_b    = (const float*)d_in[6];
    const float* Whh_b    = (const float*)d_in[7];
    const float* bih_b    = (const float*)d_in[8];
    const float* bhh_b    = (const float*)d_in[9];
    const float* W_out    = (const float*)d_in[10];
    const float* b_out    = (const float*)d_in[11];
    const float* trans    = (const float*)d_in[12];
    const float* h0       = (const float*)d_in[13];
    const float* c0       = (const float*)d_in[14];

    pre_kernel<<<TN / 64, 512>>>(sentence, embed, Wih_f, bih_f, bhh_f,
                                 Wih_b, bih_b, bhh_b);                    // 1
    dummy_kernel<<<1, 32>>>();                                            // 2
    dummy_kernel<<<1, 32>>>();                                            // 3
    lstm_kernel<<<4, 256>>>(Whh_f, Whh_b, h0, c0);                        // 4 (ncu window)
    feats_kernel<<<TN, 256>>>(W_out, b_out);                              // 5
    viterbi_fwd_kernel<<<1, 32>>>(trans);                                 // 6
    viterbi_bp_kernel<<<TN / 8, 256>>>(trans);                            // 7

    int bt_smem = TN * KT + 64;
    cudaFuncSetAttribute(viterbi_bt_kernel,
                         cudaFuncAttributeMaxDynamicSharedMemorySize, bt_smem);
    viterbi_bt_kernel<<<1, 1024, bt_smem>>>();                            // 8

    int n = out_size;
    epilogue_kernel<<<(n + 255) / 256, 256>>>((float*)d_out, n);          // 9
}

// round 13
// speedup vs baseline: 1.2468x; 1.2468x over previous
#include <cuda_runtime.h>
#include <cuda_bf16.h>
#include <math.h>

#define KT  23
#define TSTART 21
#define TSTOP  22
#define NEGV (-10000.0f)
#define TN  8192
#define EE  50
#define HHD 128
#define GG  512   // 4*HHD

// ---------------- device scratch (static, no allocations) ----------------
__device__ float d_pre[2u * TN * GG];          // 32 MB  pre-gates per dir/time
__device__ float d_houtg[2u * TN * HHD];       // 8 MB   hidden states per dir/time
__device__ float d_feats[TN * KT];             // 753 KB
__device__ float d_fvrow[TN * 32];             // 1 MB   viterbi fv rows (padded to 32)
__device__ unsigned char d_bp[TN * KT];        // 184 KB backpointers
__device__ float d_score_g;
__device__ int   d_last_tag;
__device__ int   d_tags_g[TN];

// ---------------- helpers ----------------
__device__ __forceinline__ void fma2(unsigned long long& d,
                                     unsigned long long a,
                                     unsigned long long b) {
    asm("fma.rn.f32x2 %0, %1, %2, %0;" : "+l"(d) : "l"(a), "l"(b));
}
__device__ __forceinline__ float ull_lo(unsigned long long v) {
    return __uint_as_float((unsigned)(v & 0xffffffffull));
}
__device__ __forceinline__ float ull_hi(unsigned long long v) {
    return __uint_as_float((unsigned)(v >> 32));
}
__device__ __forceinline__ float ex2f(float x) {
    float r; asm("ex2.approx.ftz.f32 %0, %1;" : "=f"(r) : "f"(x)); return r;
}
__device__ __forceinline__ float rcpf(float x) {
    float r; asm("rcp.approx.ftz.f32 %0, %1;" : "=f"(r) : "f"(x)); return r;
}
__device__ __forceinline__ unsigned smem_u32(const void* p) {
    unsigned a;
    asm("{ .reg .u64 t; cvta.to.shared.u64 t, %1; cvt.u32.u64 %0, t; }"
        : "=r"(a) : "l"(p));
    return a;
}
__device__ __forceinline__ unsigned mapa_u32(unsigned local_addr, unsigned peer_rank) {
    unsigned r;
    asm("mapa.shared::cluster.u32 %0, %1, %2;" : "=r"(r) : "r"(local_addr), "r"(peer_rank));
    return r;
}
__device__ __forceinline__ void st_remote_v4(unsigned ra,
                                             float a, float b, float c, float d) {
    asm volatile(
        "st.shared::cluster.v4.f32 [%0], {%1, %2, %3, %4};"
        :: "r"(ra), "f"(a), "f"(b), "f"(c), "f"(d) : "memory");
}
// release-store step counter into peer's flag (single thread, after __syncthreads)
__device__ __forceinline__ void flag_publish(unsigned ra_flag, unsigned val) {
    asm volatile(
        "st.release.cluster.shared::cluster.u32 [%0], %1;"
        :: "r"(ra_flag), "r"(val) : "memory");
}
// spin until local flag >= target (acquire, cluster scope)
__device__ __forceinline__ void flag_wait_ge(unsigned addr, unsigned target) {
    asm volatile(
        "{\n\t.reg .pred P;\n\t.reg .u32 v;\n\t"
        "W_%=:\n\t"
        "ld.acquire.cluster.shared::cta.u32 v, [%0];\n\t"
        "setp.lt.u32 P, v, %1;\n\t"
        "@P bra W_%=;\n\t}"
        :: "r"(addr), "r"(target) : "memory");
}

// ---------------- kernel 1: embedding + input-gate precompute ----------------
__global__ void pre_kernel(const int* __restrict__ sentence,
                           const float* __restrict__ embed,
                           const float* __restrict__ Wih_f,
                           const float* __restrict__ bih_f,
                           const float* __restrict__ bhh_f,
                           const float* __restrict__ Wih_b,
                           const float* __restrict__ bih_b,
                           const float* __restrict__ bhh_b) {
    const int TT = 64;
    __shared__ float sx[TT * EE];
    int t0 = blockIdx.x * TT;
    int tid = threadIdx.x;   // 512
    for (int idx = tid; idx < TT * EE; idx += 512) {
        int tl = idx / EE, e = idx - tl * EE;
        sx[idx] = embed[(size_t)sentence[t0 + tl] * EE + e];
    }
    __syncthreads();
    int r = tid;
    for (int d = 0; d < 2; d++) {
        const float* Wih = d ? Wih_b : Wih_f;
        const float* bi  = d ? bih_b : bih_f;
        const float* bh  = d ? bhh_b : bhh_f;
        float w[EE];
#pragma unroll
        for (int e = 0; e < EE; e++) w[e] = Wih[r * EE + e];
        float bs = bi[r] + bh[r];
        for (int tl = 0; tl < TT; tl++) {
            float acc = bs;
#pragma unroll
            for (int e = 0; e < EE; e++) acc += w[e] * sx[tl * EE + e];
            d_pre[((size_t)d * TN + (t0 + tl)) * GG + r] = acc;
        }
    }
}

// ---------------- dummy (positions ncu capture window on lstm) -------------
__global__ void dummy_kernel() {}

// ---------------- kernel 2: sequential LSTM (R11 skeleton + flag sync) -----
// 2 CTAs per direction (cluster 2). CTA q owns hidden dims [64q,64q+64).
// 256 threads = 8 warps: w=tid>>5, quad=l>>2, sub=l&3 (gate i,f,g,o).
// dim = 64q + w*8 + quad; row R = sub*128 + dim; 128 weight cols in regs.
// Per step: phase A local-half FMA, flag spin-wait for peer h, phase C
// remote-half FMA, per-lane unified activation (1 EX2 + 1 RCP), quad gather,
// cell update (sub==0), packed float4 h stores (local + remote + global),
// __syncthreads, tid0 release-stores step counter into peer's flag.
#define FMA_HALF(H0, W0) do {                                              \
    _Pragma("unroll")                                                      \
    for (int k2 = 0; k2 < 8; k2++) {                                       \
        ulonglong2 hva = h2[(H0) + 2 * k2];                                \
        ulonglong2 hvb = h2[(H0) + 2 * k2 + 1];                            \
        fma2(aA, wr[(W0) + 4 * k2 + 0], hva.x);                            \
        fma2(aB, wr[(W0) + 4 * k2 + 1], hva.y);                            \
        fma2(aA, wr[(W0) + 4 * k2 + 2], hvb.x);                            \
        fma2(aB, wr[(W0) + 4 * k2 + 3], hvb.y);                            \
    }                                                                      \
} while (0)

__global__ void __cluster_dims__(2, 1, 1) __launch_bounds__(256, 1)
lstm_kernel(const float* __restrict__ Whh_f,
            const float* __restrict__ Whh_b,
            const float* __restrict__ h0,
            const float* __restrict__ c0) {
    __shared__ float s_h[2][HHD];
    __shared__ __align__(8) unsigned s_flag;

    const int dir = blockIdx.x >> 1;
    unsigned q;
    asm("mov.u32 %0, %%cluster_ctarank;" : "=r"(q));
    const unsigned peer = q ^ 1u;

    const int tid  = threadIdx.x;
    const int w    = tid >> 5;
    const int l    = tid & 31;
    const int quad = l >> 2;
    const int sub  = l & 3;
    const int dimg = (int)(64u * q) + w * 8 + quad;   // global hidden dim
    const int R    = sub * HHD + dimg;                // gate row

    const float* Whh = dir ? Whh_b : Whh_f;

    unsigned long long wr[64];
    const unsigned long long* wrow = (const unsigned long long*)(Whh + (size_t)R * HHD);
#pragma unroll
    for (int k = 0; k < 64; k++) wr[k] = wrow[k];

    if (tid < HHD) s_h[0][tid] = h0[dir * HHD + tid];
    float c = (sub == 0) ? c0[dir * HHD + dimg] : 0.0f;

    if (tid == 0) s_flag = 0u;
    __syncthreads();
    asm volatile("barrier.cluster.arrive.aligned;" ::: "memory");
    asm volatile("barrier.cluster.wait.aligned;" ::: "memory");

    unsigned flag_addr = smem_u32(&s_flag);
    unsigned ra_flag   = mapa_u32(flag_addr, peer);

    const float* pre = d_pre + (size_t)dir * TN * GG;
    float* hout = d_houtg + (size_t)dir * TN * HHD;

    const int b16  = l & 16;
    const int dim0 = (int)(64u * q) + w * 8 + (b16 >> 2);   // storing-lane base dim
    unsigned a_loc0 = smem_u32(&s_h[0][dim0]);
    unsigned a_loc1 = smem_u32(&s_h[1][dim0]);
    unsigned a_rem0 = mapa_u32(a_loc0, peer);
    unsigned a_rem1 = mapa_u32(a_loc1, peer);

    const float LOG2E   = 1.4426950408889634f;
    const float sc_mine = (sub == 2) ? 2.0f * LOG2E : -LOG2E;   // tanh(g) vs sigmoid

    float pv_cur = pre[(size_t)(dir ? (TN - 1) : 0) * GG + R];

    for (int s = 0; s < TN; s++) {
        const int cur = s & 1;
        const int t = dir ? (TN - 1 - s) : s;
        float pv = pv_cur;
        if (s + 1 < TN)
            pv_cur = pre[(size_t)(dir ? (TN - 2 - s) : (s + 1)) * GG + R];   // prefetch

        const ulonglong2* h2 = (const ulonglong2*)s_h[cur];
        unsigned long long aA = 0ull, aB = 0ull;

        // phase A: local half (written by our own stores last step)
        if (q == 0) { FMA_HALF(0, 0); } else { FMA_HALF(16, 32); }

        // phase B: spin until peer completed >= s steps (s=0 passes, flag init 0)
        flag_wait_ge(flag_addr, (unsigned)s);

        // phase C: remote half
        if (q == 0) { FMA_HALF(16, 32); } else { FMA_HALF(0, 0); }

        float partial = (ull_lo(aA) + ull_hi(aA)) + (ull_lo(aB) + ull_hi(aB)) + pv;

        // per-lane unified nonlinearity: sigma = 1/(1+e^{-x}); tanh = 1-2/(1+e^{2x})
        float e = ex2f(sc_mine * partial);
        float dnm = rcpf(1.0f + e);
        float a = (sub == 2) ? fmaf(-2.0f, dnm, 1.0f) : dnm;

        // gather the 4 activations of this dim into the sub==0 lane
        int base = l & ~3;
        float ai = __shfl_sync(0xffffffffu, a, base);
        float af = __shfl_sync(0xffffffffu, a, base + 1);
        float ag = __shfl_sync(0xffffffffu, a, base + 2);
        float ao = __shfl_sync(0xffffffffu, a, base + 3);

        float hn = 0.0f;
        if (sub == 0) {
            c = fmaf(af, c, ai * ag);
            float e2 = ex2f(2.0f * LOG2E * c);
            float tc = fmaf(-2.0f, rcpf(1.0f + e2), 1.0f);
            hn = ao * tc;
        }

        // pack 4 hn values (quads b16/4 .. b16/4+3) into lanes 0 and 16
        float v0 = __shfl_sync(0xffffffffu, hn, b16);
        float v1 = __shfl_sync(0xffffffffu, hn, b16 + 4);
        float v2 = __shfl_sync(0xffffffffu, hn, b16 + 8);
        float v3 = __shfl_sync(0xffffffffu, hn, b16 + 12);

        if ((l & 15) == 0) {
            float4 vv = make_float4(v0, v1, v2, v3);
            *(float4*)&s_h[cur ^ 1][dim0] = vv;                       // local
            if (s + 1 < TN)
                st_remote_v4(cur ? a_rem0 : a_rem1, v0, v1, v2, v3);  // peer
            *(float4*)&hout[(size_t)t * HHD + dim0] = vv;             // global
        }
        __syncthreads();   // orders local + remote h stores CTA-wide
        if (tid == 0) flag_publish(ra_flag, (unsigned)(s + 1));
    }
    asm volatile("barrier.cluster.arrive.aligned;" ::: "memory");
    asm volatile("barrier.cluster.wait.aligned;" ::: "memory");
}

// ---------------- kernel 3: output projection ----------------
__global__ void feats_kernel(const float* __restrict__ W_out,
                             const float* __restrict__ b_out) {
    int t = blockIdx.x;
    int tid = threadIdx.x;   // 256
    __shared__ float s_hc[256];
    s_hc[tid] = (tid < HHD) ? d_houtg[(size_t)t * HHD + tid]
                            : d_houtg[(size_t)TN * HHD + (size_t)t * HHD + (tid - HHD)];
    __syncthreads();
    int w = tid >> 5, l = tid & 31;
    for (int k = w; k < KT; k += 8) {
        float acc = 0.0f;
#pragma unroll
        for (int jj = l; jj < 256; jj += 32) acc += W_out[k * 256 + jj] * s_hc[jj];
#pragma unroll
        for (int off = 16; off; off >>= 1) acc += __shfl_down_sync(0xffffffffu, acc, off);
        if (l == 0) d_feats[t * KT + k] = acc + b_out[k];
    }
}

// ---------------- kernel 4a: Viterbi forward (values only, smem fv row) ----
// Single warp, fully convergent loop (no divergence => in-order warp issue
// makes the double-buffered smem row safe without syncwarp).
__global__ void viterbi_fwd_kernel(const float* __restrict__ transitions) {
    __shared__ __align__(16) float sfv[2][32];
    int lane = threadIdx.x;
    bool act = lane < KT;

    float tr[24];
#pragma unroll
    for (int p = 0; p < KT; p++) {
        float v = NEGV;
        if (act) {
            v = transitions[lane * KT + p];
            if (lane == TSTART) v = NEGV;
            if (p == TSTOP)     v = NEGV;
        }
        tr[p] = v;
    }
    tr[23] = -3.0e38f;
    float trS = act ? ((lane == TSTOP) ? NEGV : transitions[TSTOP * KT + lane]) : NEGV;

    // init fv
    float prevfv = (lane == TSTART) ? 0.0f : NEGV;
    sfv[0][lane] = act ? prevfv : -3.0e38f;   // pad lanes 23..31 very low
    __syncwarp();

    float f0 = d_feats[0 * KT + lane];
    float f1 = d_feats[1 * KT + lane];
    float f2 = d_feats[2 * KT + lane];

    for (int t = 0; t < TN; t++) {
        int cur = t & 1;
        float fn = d_feats[(size_t)min(t + 3, TN - 1) * KT + lane];   // branch-free prefetch

        d_fvrow[t * 32 + lane] = prevfv;   // fv BEFORE step t (for bp recompute)

        const float4* vv = (const float4*)sfv[cur];
        float4 v0 = vv[0], v1 = vv[1], v2 = vv[2], v3 = vv[3], v4 = vv[4], v5 = vv[5];
        float cc[24];
        cc[0]=v0.x+tr[0];  cc[1]=v0.y+tr[1];  cc[2]=v0.z+tr[2];  cc[3]=v0.w+tr[3];
        cc[4]=v1.x+tr[4];  cc[5]=v1.y+tr[5];  cc[6]=v1.z+tr[6];  cc[7]=v1.w+tr[7];
        cc[8]=v2.x+tr[8];  cc[9]=v2.y+tr[9];  cc[10]=v2.z+tr[10];cc[11]=v2.w+tr[11];
        cc[12]=v3.x+tr[12];cc[13]=v3.y+tr[13];cc[14]=v3.z+tr[14];cc[15]=v3.w+tr[15];
        cc[16]=v4.x+tr[16];cc[17]=v4.y+tr[17];cc[18]=v4.z+tr[18];cc[19]=v4.w+tr[19];
        cc[20]=v5.x+tr[20];cc[21]=v5.y+tr[21];cc[22]=v5.z+tr[22];cc[23]=v5.w+tr[23];

        float m[12];
#pragma unroll
        for (int p = 0; p < 12; p++) m[p] = fmaxf(cc[2 * p], cc[2 * p + 1]);
#pragma unroll
        for (int p = 0; p < 6; p++) m[p] = fmaxf(m[2 * p], m[2 * p + 1]);
        float b0 = fmaxf(m[0], m[1]);
        float b1 = fmaxf(m[2], m[3]);
        float b2 = fmaxf(m[4], m[5]);
        float best = fmaxf(fmaxf(b0, b1), b2);

        float fvj = best + f0;
        prevfv = fvj;
        sfv[cur ^ 1][lane] = act ? fvj : -3.0e38f;

        f0 = f1; f1 = f2; f2 = fn;
    }

    float term = act ? (prevfv + trS) : NEGV;
    int idx = lane;
#pragma unroll
    for (int off = 16; off; off >>= 1) {
        float ov = __shfl_down_sync(0xffffffffu, term, off);
        int   oi = __shfl_down_sync(0xffffffffu, idx,  off);
        if (ov > term || (ov == term && oi < idx)) { term = ov; idx = oi; }
    }
    __syncwarp();
    if (lane == 0) { d_score_g = term; d_last_tag = idx; }
}

// ---------------- kernel 4b: backpointer recompute (parallel over t) -------
__global__ void viterbi_bp_kernel(const float* __restrict__ transitions) {
    int wrp = threadIdx.x >> 5, lane = threadIdx.x & 31;
    int t = blockIdx.x * 8 + wrp;
    if (t >= TN) return;
    int k = lane;
    bool act = k < KT;

    float tr[KT];   // tr[p] = trans[k][p] constrained
#pragma unroll
    for (int p = 0; p < KT; p++) {
        float v = NEGV;
        if (act) {
            v = __ldg(&transitions[k * KT + p]);
            if (k == TSTART) v = NEGV;
            if (p == TSTOP)  v = NEGV;
        }
        tr[p] = v;
    }
    float fvv = d_fvrow[t * 32 + lane];

    float best = __shfl_sync(0xffffffffu, fvv, 0) + tr[0];
    int bp = 0;
#pragma unroll
    for (int p = 1; p < KT; p++) {
        float v = __shfl_sync(0xffffffffu, fvv, p) + tr[p];
        if (v > best) { best = v; bp = p; }   // first-argmax semantics
    }
    if (act) d_bp[t * KT + k] = (unsigned char)bp;
}

// ---------------- kernel 4c: backtrace over smem-staged bp table -----------
__global__ void viterbi_bt_kernel() {
    extern __shared__ unsigned char sbp[];   // TN * KT bytes
    int tid = threadIdx.x;
    const uint4* src = (const uint4*)d_bp;
    uint4* dst = (uint4*)sbp;
    for (int i = tid; i < (TN * KT) / 16; i += blockDim.x) dst[i] = src[i];
    __syncthreads();
    if (tid == 0) {
        int tag = d_last_tag;
        d_tags_g[TN - 1] = tag;
        for (int t = TN - 1; t > 0; t--) {
            tag = sbp[t * KT + tag];
            d_tags_g[t - 1] = tag;
        }
    }
}

// ---------------- kernel 5: write output ----------------
__global__ void epilogue_kernel(float* __restrict__ out, int n) {
    int i = blockIdx.x * blockDim.x + threadIdx.x;
    if (i >= n) return;
    float v;
    if (n == TN) {
        v = (float)d_tags_g[i];
    } else if (n == 1) {
        v = d_score_g;
    } else {
        v = (i == 0) ? d_score_g
                     : ((i - 1 < TN) ? (float)d_tags_g[i - 1] : 0.0f);
    }
    out[i] = v;
}

// ---------------- launch ----------------
extern "C" void kernel_launch(void* const* d_in, const int* in_sizes, int n_in,
                              void* d_out, int out_size) {
    const int*   sentence = (const int*)  d_in[0];
    const float* embed    = (const float*)d_in[1];
    const float* Wih_f    = (const float*)d_in[2];
    const float* Whh_f    = (const float*)d_in[3];
    const float* bih_f    = (const float*)d_in[4];
    const float* bhh_f    = (const float*)d_in[5];
    const float* Wih_b    = (const float*)d_in[6];
    const float* Whh_b    = (const float*)d_in[7];
    const float* bih_b    = (const float*)d_in[8];
    const float* bhh_b    = (const float*)d_in[9];
    const float* W_out    = (const float*)d_in[10];
    const float* b_out    = (const float*)d_in[11];
    const float* trans    = (const float*)d_in[12];
    const float* h0       = (const float*)d_in[13];
    const float* c0       = (const float*)d_in[14];

    pre_kernel<<<TN / 64, 512>>>(sentence, embed, Wih_f, bih_f, bhh_f,
                                 Wih_b, bih_b, bhh_b);                    // 1
    dummy_kernel<<<1, 32>>>();                                            // 2
    dummy_kernel<<<1, 32>>>();                                            // 3
    lstm_kernel<<<4, 256>>>(Whh_f, Whh_b, h0, c0);                        // 4 (ncu window)
    feats_kernel<<<TN, 256>>>(W_out, b_out);                              // 5
    viterbi_fwd_kernel<<<1, 32>>>(trans);                                 // 6
    viterbi_bp_kernel<<<TN / 8, 256>>>(trans);                            // 7

    int bt_smem = TN * KT + 64;
    cudaFuncSetAttribute(viterbi_bt_kernel,
                         cudaFuncAttributeMaxDynamicSharedMemorySize, bt_smem);
    viterbi_bt_kernel<<<1, 1024, bt_smem>>>();                            // 8

    int n = out_size;
    epilogue_kernel<<<(n + 255) / 256, 256>>>((float*)d_out, n);          // 9
}